// round 1
// baseline (speedup 1.0000x reference)
#include <cuda_runtime.h>
#include <math.h>

#define D_MODEL 768
#define SEQ     2048
#define BATCH   2
#define NHEAD   12
#define DK      64
#define MTOT    (BATCH*SEQ)   /* 4096 */

// Scratch (no cudaMalloc allowed): Q,K,V projections + attention context.
__device__ float g_Q[MTOT * D_MODEL];
__device__ float g_K[MTOT * D_MODEL];
__device__ float g_V[MTOT * D_MODEL];
__device__ float g_ctx[MTOT * D_MODEL];

// ---------------------------------------------------------------------------
// GEMM body: C[M,N] = A[M,K] @ W[N,K]^T with M from grid.y, N from grid.x.
// Tiles 128x128x16, 256 threads, 8x8 micro-tile per thread.
// Row ownership  m = ty + 16*i, col ownership n = tx + 16*j  (conflict-free
// Ws reads: banks tx+16j distinct per instruction; As reads broadcast).
// ---------------------------------------------------------------------------
__device__ __forceinline__ void gemm128(const float* __restrict__ A,
                                        const float* __restrict__ W,
                                        float* __restrict__ C)
{
    __shared__ float As[16][128];
    __shared__ float Ws[16][128];

    const int tid = threadIdx.x;
    const int tx  = tid & 15;
    const int ty  = tid >> 4;
    const int bm  = blockIdx.y * 128;
    const int bn  = blockIdx.x * 128;

    float acc[8][8];
#pragma unroll
    for (int i = 0; i < 8; i++)
#pragma unroll
        for (int j = 0; j < 8; j++) acc[i][j] = 0.0f;

    for (int k0 = 0; k0 < D_MODEL; k0 += 16) {
        // Load 128x16 A-tile and 128x16 W-tile (2 float4 each per thread),
        // stored transposed: [k][m] / [k][n].
#pragma unroll
        for (int u = 0; u < 2; u++) {
            int f = tid + (u << 8);
            int r = f >> 2;
            int c = (f & 3) << 2;
            float4 va = *(const float4*)(A + (size_t)(bm + r) * D_MODEL + k0 + c);
            As[c + 0][r] = va.x; As[c + 1][r] = va.y;
            As[c + 2][r] = va.z; As[c + 3][r] = va.w;
            float4 vw = *(const float4*)(W + (size_t)(bn + r) * D_MODEL + k0 + c);
            Ws[c + 0][r] = vw.x; Ws[c + 1][r] = vw.y;
            Ws[c + 2][r] = vw.z; Ws[c + 3][r] = vw.w;
        }
        __syncthreads();

#pragma unroll
        for (int k = 0; k < 16; k++) {
            float a[8], b[8];
#pragma unroll
            for (int i = 0; i < 8; i++) a[i] = As[k][ty + (i << 4)];
#pragma unroll
            for (int j = 0; j < 8; j++) b[j] = Ws[k][tx + (j << 4)];
#pragma unroll
            for (int i = 0; i < 8; i++)
#pragma unroll
                for (int j = 0; j < 8; j++)
                    acc[i][j] = fmaf(a[i], b[j], acc[i][j]);
        }
        __syncthreads();
    }

#pragma unroll
    for (int i = 0; i < 8; i++)
#pragma unroll
        for (int j = 0; j < 8; j++)
            C[(size_t)(bm + ty + (i << 4)) * D_MODEL + bn + tx + (j << 4)] = acc[i][j];
}

// Fused Q/K/V projection: grid.z selects (input, weight, destination).
__global__ void __launch_bounds__(256)
qkv_proj_kernel(const float* __restrict__ q_in,
                const float* __restrict__ k_in,
                const float* __restrict__ v_in,
                const float* __restrict__ Wq,
                const float* __restrict__ Wk,
                const float* __restrict__ Wv)
{
    const int z = blockIdx.z;
    const float* A = (z == 0) ? q_in : (z == 1) ? k_in : v_in;
    const float* W = (z == 0) ? Wq   : (z == 1) ? Wk   : Wv;
    float*       C = (z == 0) ? g_Q  : (z == 1) ? g_K  : g_V;
    gemm128(A, W, C);
}

// Output projection: d_out = g_ctx @ Wo^T
__global__ void __launch_bounds__(256)
oproj_kernel(const float* __restrict__ Wo, float* __restrict__ out)
{
    gemm128(g_ctx, Wo, out);
}

// ---------------------------------------------------------------------------
// Flash attention over one (batch, head): Q tile 64 rows x Dk=64, stream KV
// in 64-row tiles with online softmax.  Thread (tx,ty) owns score rows
// ty*4+i (i<4) and columns tx+16*j (j<4); same mapping for O (cols = dk).
// Kst is stored transposed with an XOR-31 swizzle -> conflict-free loads and
// stores.  P tile reuses the Kst buffer (48 KB static smem total).
// ---------------------------------------------------------------------------
__global__ void __launch_bounds__(256)
attn_kernel()
{
    __shared__ float Qs [64][64];
    __shared__ float Kst[64][64];   // K transposed+swizzled; reused as P
    __shared__ float Vs [64][64];

    const int tid = threadIdx.x;
    const int tx  = tid & 15;
    const int ty  = tid >> 4;
    const int bh  = blockIdx.y;
    const int b   = bh / NHEAD;
    const int h   = bh % NHEAD;
    const int q0  = blockIdx.x * 64;

    const float* Qg = g_Q + (size_t)(b * SEQ) * D_MODEL + h * DK;
    const float* Kg = g_K + (size_t)(b * SEQ) * D_MODEL + h * DK;
    const float* Vg = g_V + (size_t)(b * SEQ) * D_MODEL + h * DK;

    // Load Q tile (coalesced; conflict-free smem stores).
#pragma unroll
    for (int u = 0; u < 16; u++) {
        int idx = tid + (u << 8);
        int r = idx >> 6, c = idx & 63;
        Qs[r][c] = Qg[(size_t)(q0 + r) * D_MODEL + c];
    }

    float o[4][4];
    float m[4], l[4];
#pragma unroll
    for (int i = 0; i < 4; i++) {
        m[i] = -1e30f; l[i] = 0.0f;
#pragma unroll
        for (int j = 0; j < 4; j++) o[i][j] = 0.0f;
    }

    for (int kt = 0; kt < SEQ; kt += 64) {
        __syncthreads();   // previous tile's P/V reads done (also covers Qs on iter 0)

        // Load K (transposed + swizzled) and V tiles.
#pragma unroll
        for (int u = 0; u < 16; u++) {
            int idx = tid + (u << 8);
            int r = idx >> 6, c = idx & 63;          // r = token, c = dk
            Kst[c][r ^ (c & 31)] = Kg[(size_t)(kt + r) * D_MODEL + c];
            Vs [r][c]            = Vg[(size_t)(kt + r) * D_MODEL + c];
        }
        __syncthreads();

        // S = (Q K^T) * 1/sqrt(Dk)
        float s[4][4];
#pragma unroll
        for (int i = 0; i < 4; i++)
#pragma unroll
            for (int j = 0; j < 4; j++) s[i][j] = 0.0f;

#pragma unroll 8
        for (int d = 0; d < 64; d++) {
            float qv[4], kv[4];
#pragma unroll
            for (int i = 0; i < 4; i++) qv[i] = Qs[ty * 4 + i][d];
#pragma unroll
            for (int j = 0; j < 4; j++)
                kv[j] = Kst[d][(tx + (j << 4)) ^ (d & 31)];
#pragma unroll
            for (int i = 0; i < 4; i++)
#pragma unroll
                for (int j = 0; j < 4; j++)
                    s[i][j] = fmaf(qv[i], kv[j], s[i][j]);
        }

        // Online softmax update (row stats replicated across the 16 tx lanes).
#pragma unroll
        for (int i = 0; i < 4; i++) {
            float tm = -1e30f;
#pragma unroll
            for (int j = 0; j < 4; j++) {
                s[i][j] *= 0.125f;                 // 1/sqrt(64)
                tm = fmaxf(tm, s[i][j]);
            }
#pragma unroll
            for (int msk = 1; msk < 16; msk <<= 1)
                tm = fmaxf(tm, __shfl_xor_sync(0xffffffffu, tm, msk));

            float mn   = fmaxf(m[i], tm);
            float corr = __expf(m[i] - mn);
            float rs   = 0.0f;
#pragma unroll
            for (int j = 0; j < 4; j++) {
                float p = __expf(s[i][j] - mn);
                s[i][j] = p;
                rs += p;
            }
#pragma unroll
            for (int msk = 1; msk < 16; msk <<= 1)
                rs += __shfl_xor_sync(0xffffffffu, rs, msk);

            l[i] = l[i] * corr + rs;
            m[i] = mn;
#pragma unroll
            for (int j = 0; j < 4; j++) o[i][j] *= corr;
        }

        __syncthreads();   // all Kst reads done -> safe to overwrite with P
        float (*Ps)[64] = Kst;
#pragma unroll
        for (int i = 0; i < 4; i++)
#pragma unroll
            for (int j = 0; j < 4; j++)
                Ps[ty * 4 + i][tx + (j << 4)] = s[i][j];
        __syncthreads();

        // O += P @ V
#pragma unroll 8
        for (int c = 0; c < 64; c++) {
            float pv[4], vv[4];
#pragma unroll
            for (int i = 0; i < 4; i++) pv[i] = Ps[ty * 4 + i][c];
#pragma unroll
            for (int j = 0; j < 4; j++) vv[j] = Vs[c][tx + (j << 4)];
#pragma unroll
            for (int i = 0; i < 4; i++)
#pragma unroll
                for (int j = 0; j < 4; j++)
                    o[i][j] = fmaf(pv[i], vv[j], o[i][j]);
        }
    }

    // Normalize and write context in [B*S, D_MODEL] layout (head h cols).
    float* Cg = g_ctx + (size_t)(b * SEQ) * D_MODEL + h * DK;
#pragma unroll
    for (int i = 0; i < 4; i++) {
        float inv = 1.0f / l[i];
#pragma unroll
        for (int j = 0; j < 4; j++)
            Cg[(size_t)(q0 + ty * 4 + i) * D_MODEL + tx + (j << 4)] = o[i][j] * inv;
    }
}

// ---------------------------------------------------------------------------
extern "C" void kernel_launch(void* const* d_in, const int* in_sizes, int n_in,
                              void* d_out, int out_size)
{
    const float* query  = (const float*)d_in[0];
    const float* key_in = (const float*)d_in[1];
    const float* value  = (const float*)d_in[2];
    const float* Wq     = (const float*)d_in[3];
    const float* Wk     = (const float*)d_in[4];
    const float* Wv     = (const float*)d_in[5];
    const float* Wo     = (const float*)d_in[6];
    float* out = (float*)d_out;

    // Q/K/V projections: 3 x (4096x768 @ 768x768^T), fused over grid.z.
    dim3 gproj(D_MODEL / 128, MTOT / 128, 3);
    qkv_proj_kernel<<<gproj, 256>>>(query, key_in, value, Wq, Wk, Wv);

    // Flash attention: 32 Q-tiles x 24 (batch*head) blocks.
    dim3 gattn(SEQ / 64, BATCH * NHEAD);
    attn_kernel<<<gattn, 256>>>();

    // Output projection into d_out.
    dim3 gout(D_MODEL / 128, MTOT / 128);
    oproj_kernel<<<gout, 256>>>(Wo, out);
}

// round 2
// speedup vs baseline: 3.9696x; 3.9696x over previous
#include <cuda_runtime.h>
#include <math.h>

#define D_MODEL 768
#define SEQ     2048
#define BATCH   2
#define NHEAD   12
#define DK      64
#define MTOT    (BATCH*SEQ)   /* 4096 */

// Scratch (no cudaMalloc allowed)
__device__ float g_Q[MTOT * D_MODEL];
__device__ float g_K[MTOT * D_MODEL];
__device__ float g_V[MTOT * D_MODEL];
__device__ float g_ctx[MTOT * D_MODEL];

// ---------------------------------------------------------------------------
// tf32 helpers
// ---------------------------------------------------------------------------
__device__ __forceinline__ unsigned f2tf(float x) {
    unsigned r;
    asm("cvt.rna.tf32.f32 %0, %1;" : "=r"(r) : "f"(x));
    return r;
}

// D += A*B  (m16n8k8, A row-major, B col-major, tf32 in, f32 accum)
__device__ __forceinline__ void mma_tf32(float d[4], const unsigned a[4], const unsigned b[2]) {
    asm volatile(
        "mma.sync.aligned.m16n8k8.row.col.f32.tf32.tf32.f32 "
        "{%0,%1,%2,%3},{%4,%5,%6,%7},{%8,%9},{%0,%1,%2,%3};"
        : "+f"(d[0]), "+f"(d[1]), "+f"(d[2]), "+f"(d[3])
        : "r"(a[0]), "r"(a[1]), "r"(a[2]), "r"(a[3]),
          "r"(b[0]), "r"(b[1]));
}

// ---------------------------------------------------------------------------
// GEMM: C[M,N] = A[M,768] @ W[N,768]^T, tile 128x128x32, 8 warps.
// Warp (wm,wn) = (warp/4 * 64, warp%4 * 32) computes 64x32 = 4x4 mma tiles.
// Smem rows padded to 36 -> all fragment LDS are bank = lane (conflict-free).
// ---------------------------------------------------------------------------
#define GPAD 36

__device__ __forceinline__ void gemm_tf32(const float* __restrict__ A,
                                          const float* __restrict__ W,
                                          float* __restrict__ C)
{
    __shared__ unsigned As[128 * GPAD];
    __shared__ unsigned Ws[128 * GPAD];

    const int tid  = threadIdx.x;
    const int lane = tid & 31;
    const int warp = tid >> 5;
    const int wm   = (warp >> 2) * 64;
    const int wn   = (warp & 3) * 32;
    const int bm   = blockIdx.y * 128;
    const int bn   = blockIdx.x * 128;

    float acc[4][4][4];
#pragma unroll
    for (int mi = 0; mi < 4; mi++)
#pragma unroll
        for (int ni = 0; ni < 4; ni++)
#pragma unroll
            for (int r = 0; r < 4; r++) acc[mi][ni][r] = 0.0f;

    for (int k0 = 0; k0 < D_MODEL; k0 += 32) {
        // stage 128x32 of A and W (float4 loads, cvt to tf32)
#pragma unroll
        for (int u = 0; u < 4; u++) {
            int idx = tid + (u << 8);
            int r = idx >> 3;
            int c = (idx & 7) << 2;
            float4 va = *(const float4*)(A + (size_t)(bm + r) * D_MODEL + k0 + c);
            As[r * GPAD + c + 0] = f2tf(va.x); As[r * GPAD + c + 1] = f2tf(va.y);
            As[r * GPAD + c + 2] = f2tf(va.z); As[r * GPAD + c + 3] = f2tf(va.w);
            float4 vw = *(const float4*)(W + (size_t)(bn + r) * D_MODEL + k0 + c);
            Ws[r * GPAD + c + 0] = f2tf(vw.x); Ws[r * GPAD + c + 1] = f2tf(vw.y);
            Ws[r * GPAD + c + 2] = f2tf(vw.z); Ws[r * GPAD + c + 3] = f2tf(vw.w);
        }
        __syncthreads();

#pragma unroll
        for (int ks = 0; ks < 4; ks++) {
            const int kk = (ks << 3) + (lane & 3);
            unsigned a[4][4], b[4][2];
#pragma unroll
            for (int mi = 0; mi < 4; mi++) {
                int row = wm + (mi << 4) + (lane >> 2);
                a[mi][0] = As[row * GPAD + kk];
                a[mi][1] = As[(row + 8) * GPAD + kk];
                a[mi][2] = As[row * GPAD + kk + 4];
                a[mi][3] = As[(row + 8) * GPAD + kk + 4];
            }
#pragma unroll
            for (int ni = 0; ni < 4; ni++) {
                int col = wn + (ni << 3) + (lane >> 2);
                b[ni][0] = Ws[col * GPAD + kk];
                b[ni][1] = Ws[col * GPAD + kk + 4];
            }
#pragma unroll
            for (int mi = 0; mi < 4; mi++)
#pragma unroll
                for (int ni = 0; ni < 4; ni++)
                    mma_tf32(acc[mi][ni], a[mi], b[ni]);
        }
        __syncthreads();
    }

    // epilogue
#pragma unroll
    for (int mi = 0; mi < 4; mi++) {
#pragma unroll
        for (int ni = 0; ni < 4; ni++) {
            int row = bm + wm + (mi << 4) + (lane >> 2);
            int col = bn + wn + (ni << 3) + ((lane & 3) << 1);
            float2 v0 = make_float2(acc[mi][ni][0], acc[mi][ni][1]);
            float2 v1 = make_float2(acc[mi][ni][2], acc[mi][ni][3]);
            *(float2*)(C + (size_t)row * D_MODEL + col)       = v0;
            *(float2*)(C + (size_t)(row + 8) * D_MODEL + col) = v1;
        }
    }
}

__global__ void __launch_bounds__(256)
qkv_proj_kernel(const float* __restrict__ q_in,
                const float* __restrict__ k_in,
                const float* __restrict__ v_in,
                const float* __restrict__ Wq,
                const float* __restrict__ Wk,
                const float* __restrict__ Wv)
{
    const int z = blockIdx.z;
    const float* A = (z == 0) ? q_in : (z == 1) ? k_in : v_in;
    const float* W = (z == 0) ? Wq   : (z == 1) ? Wk   : Wv;
    float*       C = (z == 0) ? g_Q  : (z == 1) ? g_K  : g_V;
    gemm_tf32(A, W, C);
}

__global__ void __launch_bounds__(256)
oproj_kernel(const float* __restrict__ Wo, float* __restrict__ out)
{
    gemm_tf32(g_ctx, Wo, out);
}

// ---------------------------------------------------------------------------
// Flash attention, tensor-core version.
// Block: 128 threads (4 warps), 128 q-rows per block; warp w owns rows
// [32w, 32w+32) = 2 m16 tiles. KV streamed in 64-key tiles.
// Smem (dynamic, tf32 words):
//   Qs[128][68]  (Q pre-scaled by 1/sqrt(Dk))
//   Ps[128][68]  (P = exp(S-m), per-warp rows)
//   Ks[64][68]   (K tile, row = key, col = d)   B-frag loads bank==lane
//   Vs[64][72]   (V tile, row = key, col = d)   pad 8 -> conflict-free B-frags
// ---------------------------------------------------------------------------
#define APAD 68
#define VPAD 72
#define Q_OFF 0
#define P_OFF (128 * APAD)
#define K_OFF (2 * 128 * APAD)
#define V_OFF (2 * 128 * APAD + 64 * APAD)
#define ATTN_SMEM_WORDS (2 * 128 * APAD + 64 * APAD + 64 * VPAD)

extern __shared__ unsigned sm_u[];

__global__ void __launch_bounds__(128, 2)
attn_kernel()
{
    const int tid  = threadIdx.x;
    const int lane = tid & 31;
    const int warp = tid >> 5;
    const int bh   = blockIdx.y;
    const int b    = bh / NHEAD;
    const int h    = bh % NHEAD;
    const int q0   = blockIdx.x * 128;

    unsigned* Qs = sm_u + Q_OFF;
    unsigned* Ps = sm_u + P_OFF;
    unsigned* Ks = sm_u + K_OFF;
    unsigned* Vs = sm_u + V_OFF;

    const float* Qg = g_Q + (size_t)(b * SEQ + q0) * D_MODEL + h * DK;
    const float* Kg = g_K + (size_t)(b * SEQ) * D_MODEL + h * DK;
    const float* Vg = g_V + (size_t)(b * SEQ) * D_MODEL + h * DK;

    // Load Q tile (scaled by 1/sqrt(Dk) = 0.125), 128x64.
#pragma unroll
    for (int u = 0; u < 16; u++) {
        int idx = tid + (u << 7);
        int r = idx >> 4;
        int c = (idx & 15) << 2;
        float4 v = *(const float4*)(Qg + (size_t)r * D_MODEL + c);
        Qs[r * APAD + c + 0] = f2tf(v.x * 0.125f);
        Qs[r * APAD + c + 1] = f2tf(v.y * 0.125f);
        Qs[r * APAD + c + 2] = f2tf(v.z * 0.125f);
        Qs[r * APAD + c + 3] = f2tf(v.w * 0.125f);
    }

    float o[2][8][4];
    float mrow[2][2], lrow[2][2];
#pragma unroll
    for (int mi = 0; mi < 2; mi++) {
        mrow[mi][0] = -1e30f; mrow[mi][1] = -1e30f;
        lrow[mi][0] = 0.0f;   lrow[mi][1] = 0.0f;
#pragma unroll
        for (int nt = 0; nt < 8; nt++)
#pragma unroll
            for (int r = 0; r < 4; r++) o[mi][nt][r] = 0.0f;
    }

    const int wrow = warp << 5;   // warp's base q-row in tile

    for (int kt = 0; kt < SEQ; kt += 64) {
        __syncthreads();   // previous iter's Ks/Vs reads done (covers Qs on iter 0)

        // Load K and V tiles (64x64 each)
#pragma unroll
        for (int u = 0; u < 8; u++) {
            int idx = tid + (u << 7);
            int r = idx >> 4;
            int c = (idx & 15) << 2;
            float4 kv4 = *(const float4*)(Kg + (size_t)(kt + r) * D_MODEL + c);
            Ks[r * APAD + c + 0] = f2tf(kv4.x); Ks[r * APAD + c + 1] = f2tf(kv4.y);
            Ks[r * APAD + c + 2] = f2tf(kv4.z); Ks[r * APAD + c + 3] = f2tf(kv4.w);
            float4 vv4 = *(const float4*)(Vg + (size_t)(kt + r) * D_MODEL + c);
            Vs[r * VPAD + c + 0] = f2tf(vv4.x); Vs[r * VPAD + c + 1] = f2tf(vv4.y);
            Vs[r * VPAD + c + 2] = f2tf(vv4.z); Vs[r * VPAD + c + 3] = f2tf(vv4.w);
        }
        __syncthreads();

        // S = Q K^T   (S[q][key], k-dim = d)
        float s[2][8][4];
#pragma unroll
        for (int mi = 0; mi < 2; mi++)
#pragma unroll
            for (int nt = 0; nt < 8; nt++)
#pragma unroll
                for (int r = 0; r < 4; r++) s[mi][nt][r] = 0.0f;

#pragma unroll
        for (int ks = 0; ks < 8; ks++) {
            const int kk = (ks << 3) + (lane & 3);
            unsigned a[2][4];
#pragma unroll
            for (int mi = 0; mi < 2; mi++) {
                int row = wrow + (mi << 4) + (lane >> 2);
                a[mi][0] = Qs[row * APAD + kk];
                a[mi][1] = Qs[(row + 8) * APAD + kk];
                a[mi][2] = Qs[row * APAD + kk + 4];
                a[mi][3] = Qs[(row + 8) * APAD + kk + 4];
            }
#pragma unroll
            for (int nt = 0; nt < 8; nt++) {
                int key = (nt << 3) + (lane >> 2);
                unsigned bb[2];
                bb[0] = Ks[key * APAD + kk];
                bb[1] = Ks[key * APAD + kk + 4];
                mma_tf32(s[0][nt], a[0], bb);
                mma_tf32(s[1][nt], a[1], bb);
            }
        }

        // Online softmax: rows owned = wrow+16mi+lane/4 (+8)
#pragma unroll
        for (int mi = 0; mi < 2; mi++) {
#pragma unroll
            for (int rr = 0; rr < 2; rr++) {
                float mx = -1e30f;
#pragma unroll
                for (int nt = 0; nt < 8; nt++) {
                    mx = fmaxf(mx, s[mi][nt][2 * rr]);
                    mx = fmaxf(mx, s[mi][nt][2 * rr + 1]);
                }
                mx = fmaxf(mx, __shfl_xor_sync(0xffffffffu, mx, 1));
                mx = fmaxf(mx, __shfl_xor_sync(0xffffffffu, mx, 2));
                float mnew = fmaxf(mrow[mi][rr], mx);
                float corr = __expf(mrow[mi][rr] - mnew);
                float sum = 0.0f;
#pragma unroll
                for (int nt = 0; nt < 8; nt++) {
                    float p0 = __expf(s[mi][nt][2 * rr]     - mnew);
                    float p1 = __expf(s[mi][nt][2 * rr + 1] - mnew);
                    s[mi][nt][2 * rr]     = p0;
                    s[mi][nt][2 * rr + 1] = p1;
                    sum += p0 + p1;
                }
                sum += __shfl_xor_sync(0xffffffffu, sum, 1);
                sum += __shfl_xor_sync(0xffffffffu, sum, 2);
                lrow[mi][rr] = lrow[mi][rr] * corr + sum;
                mrow[mi][rr] = mnew;
#pragma unroll
                for (int nt = 0; nt < 8; nt++) {
                    o[mi][nt][2 * rr]     *= corr;
                    o[mi][nt][2 * rr + 1] *= corr;
                }
            }
        }

        // Store P (own warp rows) in A-fragment layout
#pragma unroll
        for (int mi = 0; mi < 2; mi++) {
            int row = wrow + (mi << 4) + (lane >> 2);
#pragma unroll
            for (int nt = 0; nt < 8; nt++) {
                int col = (nt << 3) + ((lane & 3) << 1);
                Ps[row * APAD + col]           = f2tf(s[mi][nt][0]);
                Ps[row * APAD + col + 1]       = f2tf(s[mi][nt][1]);
                Ps[(row + 8) * APAD + col]     = f2tf(s[mi][nt][2]);
                Ps[(row + 8) * APAD + col + 1] = f2tf(s[mi][nt][3]);
            }
        }
        __syncwarp();

        // O += P V   (k-dim = key, n-dim = d)
#pragma unroll
        for (int ks = 0; ks < 8; ks++) {
            const int kk = (ks << 3) + (lane & 3);
            unsigned a[2][4];
#pragma unroll
            for (int mi = 0; mi < 2; mi++) {
                int row = wrow + (mi << 4) + (lane >> 2);
                a[mi][0] = Ps[row * APAD + kk];
                a[mi][1] = Ps[(row + 8) * APAD + kk];
                a[mi][2] = Ps[row * APAD + kk + 4];
                a[mi][3] = Ps[(row + 8) * APAD + kk + 4];
            }
#pragma unroll
            for (int nt = 0; nt < 8; nt++) {
                int dcol = (nt << 3) + (lane >> 2);
                unsigned bb[2];
                bb[0] = Vs[kk * VPAD + dcol];
                bb[1] = Vs[(kk + 4) * VPAD + dcol];
                mma_tf32(o[0][nt], a[0], bb);
                mma_tf32(o[1][nt], a[1], bb);
            }
        }
    }

    // Epilogue: normalize, write context [B*S, D_MODEL] (head h columns)
    float* Cg = g_ctx + (size_t)(b * SEQ + q0) * D_MODEL + h * DK;
#pragma unroll
    for (int mi = 0; mi < 2; mi++) {
        int row = wrow + (mi << 4) + (lane >> 2);
        float inv0 = 1.0f / lrow[mi][0];
        float inv1 = 1.0f / lrow[mi][1];
#pragma unroll
        for (int nt = 0; nt < 8; nt++) {
            int col = (nt << 3) + ((lane & 3) << 1);
            float2 v0 = make_float2(o[mi][nt][0] * inv0, o[mi][nt][1] * inv0);
            float2 v1 = make_float2(o[mi][nt][2] * inv1, o[mi][nt][3] * inv1);
            *(float2*)(Cg + (size_t)row * D_MODEL + col)       = v0;
            *(float2*)(Cg + (size_t)(row + 8) * D_MODEL + col) = v1;
        }
    }
}

// ---------------------------------------------------------------------------
extern "C" void kernel_launch(void* const* d_in, const int* in_sizes, int n_in,
                              void* d_out, int out_size)
{
    const float* query  = (const float*)d_in[0];
    const float* key_in = (const float*)d_in[1];
    const float* value  = (const float*)d_in[2];
    const float* Wq     = (const float*)d_in[3];
    const float* Wk     = (const float*)d_in[4];
    const float* Wv     = (const float*)d_in[5];
    const float* Wo     = (const float*)d_in[6];
    float* out = (float*)d_out;

    const int attn_smem = ATTN_SMEM_WORDS * 4;   // ~105 KB
    cudaFuncSetAttribute(attn_kernel,
                         cudaFuncAttributeMaxDynamicSharedMemorySize, attn_smem);

    dim3 gproj(D_MODEL / 128, MTOT / 128, 3);
    qkv_proj_kernel<<<gproj, 256>>>(query, key_in, value, Wq, Wk, Wv);

    dim3 gattn(SEQ / 128, BATCH * NHEAD);
    attn_kernel<<<gattn, 128, attn_smem>>>();

    dim3 gout(D_MODEL / 128, MTOT / 128);
    oproj_kernel<<<gout, 256>>>(Wo, out);
}